// round 16
// baseline (speedup 1.0000x reference)
#include <cuda_runtime.h>

// GRU: B=4096, T=512, I=32, H=64. out = final hidden (B, H) fp32.
// 256 CTAs x 256 threads, __launch_bounds__(256,2) -> 2 CTAs/SM on busy SMs:
// two INDEPENDENT per-step chains interleave per SMSP (cross-CTA latency
// hiding) with no extra weight traffic per warp. Per CTA: 16 rows; per SMSP
// s: 2 warps owning 4 rows (r0=4s):
//   h0 (half=0): GEMM h-k[0,48); ships rows 2,3 (R,Z,N); stages x(t+1);
//                epilogue rows 0,1.
//   h1 (half=1): GEMM h-k[48,64) + x-k[0,32) (XD parity buf, separate Nh/Nx
//                accums); ships rows 0,1 (R,Z,Nh,Nx); epilogue rows 2,3.
// Two per-smsp named barriers per step (64 threads each, CTA-scoped).
// Math: packed fma.rn.f32x2 on duplicated smem operands (dup layout k*36+2r).

#define THREADS      256
#define ROWS_PER_CTA 16
#define I_DIM        32
#define H_DIM        64
#define G_DIM        192
#define S_DUP        36

#define WS_FLOATS    (96 * G_DIM)      // 18432
#define HD_FLOATS    (H_DIM * S_DUP)   // 2304
#define XD_FLOATS    (I_DIM * S_DUP)   // 1152 (x2 parity buffers)
#define SC_U64       (4 * 4 * 4 * 32)  // l, acc, smsp, lane = 2048
#define SMEM_BYTES   ((WS_FLOATS + HD_FLOATS + 2 * XD_FLOATS) * 4 + SC_U64 * 8)

typedef unsigned long long u64;

__device__ __forceinline__ void fma2(u64& d, u64 a, u64 b) {
    asm("fma.rn.f32x2 %0, %1, %2, %0;" : "+l"(d) : "l"(a), "l"(b));
}
__device__ __forceinline__ u64 add2(u64 a, u64 b) {
    u64 r;
    asm("add.rn.f32x2 %0, %1, %2;" : "=l"(r) : "l"(a), "l"(b));
    return r;
}
__device__ __forceinline__ float2 upk(u64 v) {
    float2 f;
    asm("mov.b64 {%0, %1}, %2;" : "=f"(f.x), "=f"(f.y) : "l"(v));
    return f;
}
__device__ __forceinline__ float tanh_hw(float x) {
    float y;
    asm("tanh.approx.f32 %0, %1;" : "=f"(y) : "f"(x));
    return y;
}
__device__ __forceinline__ float sig_hw(float x) {
    return fmaf(tanh_hw(0.5f * x), 0.5f, 0.5f);
}
__device__ __forceinline__ float tanh_acc(float x) {
    return __fdividef(2.0f, 1.0f + __expf(-2.0f * x)) - 1.0f;
}
__device__ __forceinline__ void barx(int id) {
    asm volatile("bar.sync %0, %1;" :: "r"(id), "r"(64) : "memory");
}

struct GateB { float bR0, bR1, bZ0, bZ1, bIN0, bIN1, bHN0, bHN1; };

__device__ __forceinline__ void gate_row(u64 sR, u64 sZ, u64 sN, u64 sX,
                                         const GateB& b, float2& h01) {
    float2 uR = upk(sR), uZ = upk(sZ), uH = upk(sN), uX = upk(sX);
    float r0g = sig_hw(uR.x + b.bR0);
    float z0g = sig_hw(uZ.x + b.bZ0);
    float n0  = tanh_acc(uX.x + b.bIN0 + r0g * (uH.x + b.bHN0));
    float r1g = sig_hw(uR.y + b.bR1);
    float z1g = sig_hw(uZ.y + b.bZ1);
    float n1  = tanh_acc(uX.y + b.bIN1 + r1g * (uH.y + b.bHN1));
    h01.x = n0 + z0g * (h01.x - n0);
    h01.y = n1 + z1g * (h01.y - n1);
}

// 4-row GEMM k-step: ab = A base (dup layout, row folded), wb = &Ws[k*G_DIM+j0]
#define KG4(ab, wb, R, Z, N)                                                 \
    {                                                                        \
        ulonglong2 A0 = *reinterpret_cast<const ulonglong2*>(ab);            \
        ulonglong2 A1 = *reinterpret_cast<const ulonglong2*>((ab) + 4);      \
        u64 wr = *reinterpret_cast<const u64*>(wb);                          \
        u64 wz = *reinterpret_cast<const u64*>((wb) + 64);                   \
        u64 wn = *reinterpret_cast<const u64*>((wb) + 128);                  \
        fma2(R[0], A0.x, wr); fma2(R[1], A0.y, wr);                          \
        fma2(R[2], A1.x, wr); fma2(R[3], A1.y, wr);                          \
        fma2(Z[0], A0.x, wz); fma2(Z[1], A0.y, wz);                          \
        fma2(Z[2], A1.x, wz); fma2(Z[3], A1.y, wz);                          \
        fma2(N[0], A0.x, wn); fma2(N[1], A0.y, wn);                          \
        fma2(N[2], A1.x, wn); fma2(N[3], A1.y, wn);                          \
    }

// SC slot: l (0..3 local row), a (0..3 acc)
#define SCI(l, a)  ((((l) * 4 + (a)) * 4 + s) * 32 + c)

__global__ void __launch_bounds__(THREADS, 2)
gru_fwd_kernel(const float* __restrict__ seq,
               const float* __restrict__ W_ih,
               const float* __restrict__ W_hh,
               const float* __restrict__ b_ih,
               const float* __restrict__ b_hh,
               float* __restrict__ out,
               int B, int T)
{
    extern __shared__ float sm[];
    float* Ws  = sm;
    float* HD  = sm + WS_FLOATS;
    float* XD  = HD + HD_FLOATS;                 // 2 parity buffers
    u64*   SCb = (u64*)(XD + 2 * XD_FLOATS);

    const int tid = threadIdx.x;
    const int w   = tid >> 5;
    const int c   = tid & 31;
    const int s   = w & 3;                       // SMSP group
    const bool kodd = (w >> 2);                  // 0: k[0,48), 1: k[48,96)
    const int bb  = blockIdx.x * ROWS_PER_CTA;
    const int r0  = s * 4;
    const int j0  = 2 * c;
    const int bid = 1 + s;

    // ---- one-time init ----
    for (int idx = tid; idx < G_DIM * H_DIM; idx += THREADS) {
        int gg = idx / H_DIM, k = idx % H_DIM;
        Ws[k * G_DIM + gg] = W_hh[idx];
    }
    for (int idx = tid; idx < G_DIM * I_DIM; idx += THREADS) {
        int gg = idx / I_DIM, i = idx % I_DIM;
        Ws[(H_DIM + i) * G_DIM + gg] = W_ih[idx];
    }
    for (int idx = tid; idx < HD_FLOATS; idx += THREADS) HD[idx] = 0.0f;

    GateB gb;
    gb.bR0  = b_ih[j0]      + b_hh[j0];
    gb.bR1  = b_ih[j0 + 1]  + b_hh[j0 + 1];
    gb.bZ0  = b_ih[64 + j0] + b_hh[64 + j0];
    gb.bZ1  = b_ih[65 + j0] + b_hh[65 + j0];
    gb.bIN0 = b_ih[128 + j0]; gb.bIN1 = b_ih[129 + j0];
    gb.bHN0 = b_hh[128 + j0]; gb.bHN1 = b_hh[129 + j0];

    // geometry
    const int rr  = 2 * r0;                      // A row float offset (4 rows)
    const int hw0 = j0 * S_DUP;
    const int hw1 = (j0 + 1) * S_DUP;

    // h0 stager role: lane c stages row r0+(c>>3), cols (c&7)*4 .. +4
    const int srow  = r0 + (c >> 3);
    const int scol4 = (c & 7) * 4;
    const int xdw   = scol4 * S_DUP + 2 * srow;
    const float* xptr = seq + (size_t)(bb + srow) * T * I_DIM + scol4;

    float2 hh0 = make_float2(0.f, 0.f), hh1 = hh0;

    // ---- prologue: h0 warps stage x(0) -> XD[0] ----
    if (!kodd) {
        float4 v0 = *reinterpret_cast<const float4*>(xptr);
        #pragma unroll
        for (int i = 0; i < 4; ++i) {
            float vv = (&v0.x)[i];
            *reinterpret_cast<float2*>(&XD[xdw + i * S_DUP]) = make_float2(vv, vv);
        }
    }
    __syncthreads();

    // ---- main loop ----
    for (int t = 0; t < T; ++t) {
        const int par = t & 1;

        if (!kodd) {
            // ======== h0: prefetch x(t+1); GEMM h-k[0,48); ship rows 2,3 ====
            float4 pf;
            const bool ld = (t + 1 < T);
            if (ld) pf = *reinterpret_cast<const float4*>(xptr + (size_t)(t + 1) * I_DIM);

            u64 R[4] = {0, 0, 0, 0}, Z[4] = {0, 0, 0, 0}, N[4] = {0, 0, 0, 0};
            {
                const float* hb = HD + rr;
                const float* wb = Ws + j0;
                #pragma unroll 8
                for (int k = 0; k < 48; ++k) {
                    KG4(hb, wb, R, Z, N)
                    hb += S_DUP; wb += G_DIM;
                }
            }
            SCb[SCI(2, 0)] = R[2]; SCb[SCI(2, 1)] = Z[2]; SCb[SCI(2, 2)] = N[2];
            SCb[SCI(3, 0)] = R[3]; SCb[SCI(3, 1)] = Z[3]; SCb[SCI(3, 2)] = N[3];
            barx(bid);

            // ======== phase 2: stage x(t+1) -> XD[par^1]; epilogue rows 0,1 =
            if (ld) {
                float* dst = XD + (par ^ 1) * XD_FLOATS + xdw;
                #pragma unroll
                for (int i = 0; i < 4; ++i) {
                    float vv = (&pf.x)[i];
                    *reinterpret_cast<float2*>(dst + i * S_DUP) = make_float2(vv, vv);
                }
            }
            {
                u64 sR = add2(R[0], SCb[SCI(0, 0)]);
                u64 sZ = add2(Z[0], SCb[SCI(0, 1)]);
                u64 sN = add2(N[0], SCb[SCI(0, 2)]);
                u64 sX = SCb[SCI(0, 3)];
                gate_row(sR, sZ, sN, sX, gb, hh0);
                const int gr2 = 2 * (r0 + 0);
                *reinterpret_cast<float2*>(&HD[hw0 + gr2]) = make_float2(hh0.x, hh0.x);
                *reinterpret_cast<float2*>(&HD[hw1 + gr2]) = make_float2(hh0.y, hh0.y);
            }
            {
                u64 sR = add2(R[1], SCb[SCI(1, 0)]);
                u64 sZ = add2(Z[1], SCb[SCI(1, 1)]);
                u64 sN = add2(N[1], SCb[SCI(1, 2)]);
                u64 sX = SCb[SCI(1, 3)];
                gate_row(sR, sZ, sN, sX, gb, hh1);
                const int gr2 = 2 * (r0 + 1);
                *reinterpret_cast<float2*>(&HD[hw0 + gr2]) = make_float2(hh1.x, hh1.x);
                *reinterpret_cast<float2*>(&HD[hw1 + gr2]) = make_float2(hh1.y, hh1.y);
            }
            barx(bid);
        } else {
            // ======== h1: GEMM h-k[48,64) + x-k[0,32); ship rows 0,1 ========
            u64 R[4]  = {0, 0, 0, 0}, Z[4]  = {0, 0, 0, 0};
            u64 Nh[4] = {0, 0, 0, 0}, Nx[4] = {0, 0, 0, 0};
            {
                const float* hb = HD + 48 * S_DUP + rr;
                const float* wb = Ws + 48 * G_DIM + j0;
                #pragma unroll 8
                for (int k = 0; k < 16; ++k) {
                    KG4(hb, wb, R, Z, Nh)
                    hb += S_DUP; wb += G_DIM;
                }
            }
            {
                const float* xb = XD + par * XD_FLOATS + rr;
                const float* wb = Ws + H_DIM * G_DIM + j0;
                #pragma unroll 8
                for (int k = 0; k < I_DIM; ++k) {
                    KG4(xb, wb, R, Z, Nx)
                    xb += S_DUP; wb += G_DIM;
                }
            }
            SCb[SCI(0, 0)] = R[0]; SCb[SCI(0, 1)] = Z[0];
            SCb[SCI(0, 2)] = Nh[0]; SCb[SCI(0, 3)] = Nx[0];
            SCb[SCI(1, 0)] = R[1]; SCb[SCI(1, 1)] = Z[1];
            SCb[SCI(1, 2)] = Nh[1]; SCb[SCI(1, 3)] = Nx[1];
            barx(bid);

            // ======== phase 2: epilogue rows 2,3 ============================
            {
                u64 sR = add2(SCb[SCI(2, 0)], R[2]);
                u64 sZ = add2(SCb[SCI(2, 1)], Z[2]);
                u64 sN = add2(SCb[SCI(2, 2)], Nh[2]);
                u64 sX = Nx[2];
                gate_row(sR, sZ, sN, sX, gb, hh0);
                const int gr2 = 2 * (r0 + 2);
                *reinterpret_cast<float2*>(&HD[hw0 + gr2]) = make_float2(hh0.x, hh0.x);
                *reinterpret_cast<float2*>(&HD[hw1 + gr2]) = make_float2(hh0.y, hh0.y);
            }
            {
                u64 sR = add2(SCb[SCI(3, 0)], R[3]);
                u64 sZ = add2(SCb[SCI(3, 1)], Z[3]);
                u64 sN = add2(SCb[SCI(3, 2)], Nh[3]);
                u64 sX = Nx[3];
                gate_row(sR, sZ, sN, sX, gb, hh1);
                const int gr2 = 2 * (r0 + 3);
                *reinterpret_cast<float2*>(&HD[hw0 + gr2]) = make_float2(hh1.x, hh1.x);
                *reinterpret_cast<float2*>(&HD[hw1 + gr2]) = make_float2(hh1.y, hh1.y);
            }
            barx(bid);
        }
    }

    // ---- final output: each warp owns 2 rows ----
    const int lbase = kodd ? 2 : 0;
    const int g0 = bb + r0 + lbase;
    *reinterpret_cast<float2*>(&out[(size_t)(g0 + 0) * H_DIM + j0]) = hh0;
    *reinterpret_cast<float2*>(&out[(size_t)(g0 + 1) * H_DIM + j0]) = hh1;
}

extern "C" void kernel_launch(void* const* d_in, const int* in_sizes, int n_in,
                              void* d_out, int out_size) {
    const float* seq  = (const float*)d_in[0];
    const float* W_ih = (const float*)d_in[1];
    const float* W_hh = (const float*)d_in[2];
    const float* b_ih = (const float*)d_in[3];
    const float* b_hh = (const float*)d_in[4];
    float* out = (float*)d_out;

    const int B = out_size / H_DIM;
    const int T = in_sizes[0] / (B * I_DIM);

    cudaFuncSetAttribute(gru_fwd_kernel,
                         cudaFuncAttributeMaxDynamicSharedMemorySize, SMEM_BYTES);

    const int grid = (B + ROWS_PER_CTA - 1) / ROWS_PER_CTA;   // 256
    gru_fwd_kernel<<<grid, THREADS, SMEM_BYTES>>>(seq, W_ih, W_hh, b_ih, b_hh,
                                                  out, B, T);
}

// round 17
// speedup vs baseline: 1.1853x; 1.1853x over previous
#include <cuda_runtime.h>

// GRU: B=4096, T=512, I=32, H=64. out = final hidden (B, H) fp32.
// R6 champion structure + surgical epilogue cuts:
//   - n-gate via hw tanh.approx (r/z already use it; measured err ~1e-7)
//   - epilogue SC/XP loads batched up front (overlapped LDS latencies)
// 128 CTAs x 384 threads. Per SMSP s: 2 h-warps (recurrent GEMM k-split
// 32/32, epilogue rows 0-2 / 3-5) + 1 x-warp (XP(t+1) one step ahead,
// epilogue rows 6-7). Per-smsp named barriers. Math: packed fma.rn.f32x2.

#define THREADS      384
#define ROWS_PER_CTA 32
#define I_DIM        32
#define H_DIM        64
#define G_DIM        192
#define S_DUP        68

#define WS_FLOATS    (96 * G_DIM)        // 18432
#define HD_FLOATS    (H_DIM * S_DUP)     // 4352
#define XD_FLOATS    (I_DIM * S_DUP)     // 2176 (x2 buffers)
#define SC_U64       (2 * 4 * 8 * 3 * 32)   // contrib, smsp, row, acc, lane
#define XP_U64       (2 * 4 * 6 * 3 * 32)   // parity, smsp, row0-5, acc, lane
#define SMEM_BYTES   ((WS_FLOATS + HD_FLOATS + 2 * XD_FLOATS) * 4 + (SC_U64 + XP_U64) * 8)

typedef unsigned long long u64;

__device__ __forceinline__ void fma2(u64& d, u64 a, u64 b) {
    asm("fma.rn.f32x2 %0, %1, %2, %0;" : "+l"(d) : "l"(a), "l"(b));
}
__device__ __forceinline__ u64 add2(u64 a, u64 b) {
    u64 r;
    asm("add.rn.f32x2 %0, %1, %2;" : "=l"(r) : "l"(a), "l"(b));
    return r;
}
__device__ __forceinline__ float2 upk(u64 v) {
    float2 f;
    asm("mov.b64 {%0, %1}, %2;" : "=f"(f.x), "=f"(f.y) : "l"(v));
    return f;
}
__device__ __forceinline__ float tanh_hw(float x) {
    float y;
    asm("tanh.approx.f32 %0, %1;" : "=f"(y) : "f"(x));
    return y;
}
__device__ __forceinline__ float sig_hw(float x) {
    return fmaf(tanh_hw(0.5f * x), 0.5f, 0.5f);
}
__device__ __forceinline__ void barx(int id) {
    asm volatile("bar.sync %0, %1;" :: "r"(id), "r"(96) : "memory");
}

struct GateB { float bR0, bR1, bZ0, bZ1, bIN0, bIN1, bHN0, bHN1; };

// gate math with hw tanh for ALL gates (n-gate chain 45cyc -> 1 MUFU)
__device__ __forceinline__ void gate_row(u64 sR, u64 sZ, u64 sN, u64 sX,
                                         const GateB& b, float2& h01) {
    float2 uR = upk(sR), uZ = upk(sZ), uH = upk(sN), uX = upk(sX);
    float r0g = sig_hw(uR.x + b.bR0);
    float z0g = sig_hw(uZ.x + b.bZ0);
    float n0  = tanh_hw(uX.x + b.bIN0 + r0g * (uH.x + b.bHN0));
    float r1g = sig_hw(uR.y + b.bR1);
    float z1g = sig_hw(uZ.y + b.bZ1);
    float n1  = tanh_hw(uX.y + b.bIN1 + r1g * (uH.y + b.bHN1));
    h01.x = n0 + z0g * (h01.x - n0);
    h01.y = n1 + z1g * (h01.y - n1);
}

// recurrent k-step: 8 rows, acc (aR, aZ, aN), A from HD
#define KSTEP_H(kk)                                                          \
    {                                                                        \
        const float* hk = &HD[(kk) * S_DUP + 2 * r0];                        \
        ulonglong2 A0 = *reinterpret_cast<const ulonglong2*>(hk);            \
        ulonglong2 A1 = *reinterpret_cast<const ulonglong2*>(hk + 4);        \
        ulonglong2 A2 = *reinterpret_cast<const ulonglong2*>(hk + 8);        \
        ulonglong2 A3 = *reinterpret_cast<const ulonglong2*>(hk + 12);       \
        const float* wk = &Ws[(kk) * G_DIM + j0];                            \
        u64 wr = *reinterpret_cast<const u64*>(wk);                          \
        u64 wz = *reinterpret_cast<const u64*>(wk + 64);                     \
        u64 wn = *reinterpret_cast<const u64*>(wk + 128);                    \
        fma2(aR[0], A0.x, wr); fma2(aR[1], A0.y, wr);                        \
        fma2(aR[2], A1.x, wr); fma2(aR[3], A1.y, wr);                        \
        fma2(aR[4], A2.x, wr); fma2(aR[5], A2.y, wr);                        \
        fma2(aR[6], A3.x, wr); fma2(aR[7], A3.y, wr);                        \
        fma2(aZ[0], A0.x, wz); fma2(aZ[1], A0.y, wz);                        \
        fma2(aZ[2], A1.x, wz); fma2(aZ[3], A1.y, wz);                        \
        fma2(aZ[4], A2.x, wz); fma2(aZ[5], A2.y, wz);                        \
        fma2(aZ[6], A3.x, wz); fma2(aZ[7], A3.y, wz);                        \
        fma2(aN[0], A0.x, wn); fma2(aN[1], A0.y, wn);                        \
        fma2(aN[2], A1.x, wn); fma2(aN[3], A1.y, wn);                        \
        fma2(aN[4], A2.x, wn); fma2(aN[5], A2.y, wn);                        \
        fma2(aN[6], A3.x, wn); fma2(aN[7], A3.y, wn);                        \
    }

// x-projection k-step: 8 rows, acc (aR, aZ, aX), A from XDp
#define KSTEP_X(kk, P)                                                       \
    {                                                                        \
        const float* xk = &(P)[(kk) * S_DUP + 2 * r0];                       \
        ulonglong2 A0 = *reinterpret_cast<const ulonglong2*>(xk);            \
        ulonglong2 A1 = *reinterpret_cast<const ulonglong2*>(xk + 4);        \
        ulonglong2 A2 = *reinterpret_cast<const ulonglong2*>(xk + 8);        \
        ulonglong2 A3 = *reinterpret_cast<const ulonglong2*>(xk + 12);       \
        const float* wk = &Ws[(H_DIM + (kk)) * G_DIM + j0];                  \
        u64 wr = *reinterpret_cast<const u64*>(wk);                          \
        u64 wz = *reinterpret_cast<const u64*>(wk + 64);                     \
        u64 wn = *reinterpret_cast<const u64*>(wk + 128);                    \
        fma2(aR[0], A0.x, wr); fma2(aR[1], A0.y, wr);                        \
        fma2(aR[2], A1.x, wr); fma2(aR[3], A1.y, wr);                        \
        fma2(aR[4], A2.x, wr); fma2(aR[5], A2.y, wr);                        \
        fma2(aR[6], A3.x, wr); fma2(aR[7], A3.y, wr);                        \
        fma2(aZ[0], A0.x, wz); fma2(aZ[1], A0.y, wz);                        \
        fma2(aZ[2], A1.x, wz); fma2(aZ[3], A1.y, wz);                        \
        fma2(aZ[4], A2.x, wz); fma2(aZ[5], A2.y, wz);                        \
        fma2(aZ[6], A3.x, wz); fma2(aZ[7], A3.y, wz);                        \
        fma2(aX[0], A0.x, wn); fma2(aX[1], A0.y, wn);                        \
        fma2(aX[2], A1.x, wn); fma2(aX[3], A1.y, wn);                        \
        fma2(aX[4], A2.x, wn); fma2(aX[5], A2.y, wn);                        \
        fma2(aX[6], A3.x, wn); fma2(aX[7], A3.y, wn);                        \
    }

#define SCI(g, l, a)  (((((g) * 4 + smsp) * 8 + (l)) * 3 + (a)) * 32 + c)
#define XPI(p, l, a)  (((((p) * 4 + smsp) * 6 + (l)) * 3 + (a)) * 32 + c)

#define HDWR(gr, hv)                                                                \
    *reinterpret_cast<float2*>(&HD[j0 * S_DUP + 2 * (gr)])       = make_float2((hv).x, (hv).x); \
    *reinterpret_cast<float2*>(&HD[(j0 + 1) * S_DUP + 2 * (gr)]) = make_float2((hv).y, (hv).y);

__global__ void __launch_bounds__(THREADS, 1)
gru_fwd_kernel(const float* __restrict__ seq,
               const float* __restrict__ W_ih,
               const float* __restrict__ W_hh,
               const float* __restrict__ b_ih,
               const float* __restrict__ b_hh,
               float* __restrict__ out,
               int B, int T)
{
    extern __shared__ float sm[];
    float* Ws  = sm;
    float* HD  = sm + WS_FLOATS;
    float* XD  = HD + HD_FLOATS;                    // 2 parity buffers
    u64*   SCb = (u64*)(XD + 2 * XD_FLOATS);
    u64*   XPb = SCb + SC_U64;

    const int tid  = threadIdx.x;
    const int w    = tid >> 5;
    const int c    = tid & 31;
    const int smsp = (w < 8) ? (w & 3) : (w - 8);
    const int grp  = w >> 2;                        // 0,1: h-warps, 2: x-warp
    const int bb   = blockIdx.x * ROWS_PER_CTA;
    const int r0   = smsp * 8;
    const int j0   = 2 * c;
    const int barid = 1 + smsp;

    // ---- one-time init ----
    for (int idx = tid; idx < G_DIM * H_DIM; idx += THREADS) {
        int gg = idx / H_DIM, k = idx % H_DIM;
        Ws[k * G_DIM + gg] = W_hh[idx];
    }
    for (int idx = tid; idx < G_DIM * I_DIM; idx += THREADS) {
        int gg = idx / I_DIM, i = idx % I_DIM;
        Ws[(H_DIM + i) * G_DIM + gg] = W_ih[idx];
    }
    for (int idx = tid; idx < HD_FLOATS; idx += THREADS) HD[idx] = 0.0f;

    GateB gb;
    gb.bR0  = b_ih[j0]      + b_hh[j0];
    gb.bR1  = b_ih[j0 + 1]  + b_hh[j0 + 1];
    gb.bZ0  = b_ih[64 + j0] + b_hh[64 + j0];
    gb.bZ1  = b_ih[65 + j0] + b_hh[65 + j0];
    gb.bIN0 = b_ih[128 + j0]; gb.bIN1 = b_ih[129 + j0];
    gb.bHN0 = b_hh[128 + j0]; gb.bHN1 = b_hh[129 + j0];

    // stager role (h-warps only): 64 slots/smsp = 8 rows x 8 float4 chunks
    const int q     = (grp == 1 ? 32 : 0) + c;
    const int srow  = r0 + (q >> 3);
    const int scol4 = (q & 7) * 4;
    const float* xptr = seq + (size_t)(bb + srow) * T * I_DIM + scol4;

    float2 h0r = make_float2(0.f, 0.f), h1r = h0r, h2r = h0r;
    u64 pR6 = 0, pZ6 = 0, pX6 = 0, pR7 = 0, pZ7 = 0, pX7 = 0;   // x-warp prev

    // prologue: stage x(0) -> XD[0], x(1) -> XD[1]
    if (w < 8) {
        float4 v0 = *reinterpret_cast<const float4*>(xptr);
        #pragma unroll
        for (int i = 0; i < 4; ++i) {
            float vv = (&v0.x)[i];
            *reinterpret_cast<float2*>(&XD[(scol4 + i) * S_DUP + 2 * srow]) =
                make_float2(vv, vv);
        }
        if (T > 1) {
            float4 v1 = *reinterpret_cast<const float4*>(xptr + I_DIM);
            #pragma unroll
            for (int i = 0; i < 4; ++i) {
                float vv = (&v1.x)[i];
                *reinterpret_cast<float2*>(&XD[XD_FLOATS + (scol4 + i) * S_DUP + 2 * srow]) =
                    make_float2(vv, vv);
            }
        }
    }
    __syncthreads();

    // prologue: x-warps compute XP(0) into parity 0
    if (w >= 8) {
        u64 aR[8], aZ[8], aX[8];
        #pragma unroll
        for (int i = 0; i < 8; ++i) { aR[i] = 0; aZ[i] = 0; aX[i] = 0; }
        const float* XDp = XD;
        #pragma unroll 8
        for (int k = 0; k < I_DIM; ++k) KSTEP_X(k, XDp)
        #pragma unroll
        for (int l = 0; l < 6; ++l) {
            XPb[XPI(0, l, 0)] = aR[l];
            XPb[XPI(0, l, 1)] = aZ[l];
            XPb[XPI(0, l, 2)] = aX[l];
        }
        pR6 = aR[6]; pZ6 = aZ[6]; pX6 = aX[6];
        pR7 = aR[7]; pZ7 = aZ[7]; pX7 = aX[7];
    }
    __syncthreads();

    for (int t = 0; t < T; ++t) {
        const int par  = t & 1;          // XP parity for this step's epilogue
        const int par2 = (t + 1) & 1;    // XP parity written by x-warp

        if (w < 8) {
            // x(t+2) prefetch
            float4 xn4 = make_float4(0.f, 0.f, 0.f, 0.f);
            if (t + 2 < T)
                xn4 = *reinterpret_cast<const float4*>(xptr + (size_t)(t + 2) * I_DIM);

            u64 aR[8], aZ[8], aN[8];
            #pragma unroll
            for (int i = 0; i < 8; ++i) { aR[i] = 0; aZ[i] = 0; aN[i] = 0; }
            const int koff = grp * 32;
            #pragma unroll 8
            for (int k = 0; k < 32; ++k) KSTEP_H(koff + k)

            if (grp == 0) {
                #pragma unroll
                for (int l = 3; l < 8; ++l) {
                    SCb[SCI(0, l, 0)] = aR[l];
                    SCb[SCI(0, l, 1)] = aZ[l];
                    SCb[SCI(0, l, 2)] = aN[l];
                }
            } else {
                SCb[SCI(1, 0, 0)] = aR[0]; SCb[SCI(1, 0, 1)] = aZ[0]; SCb[SCI(1, 0, 2)] = aN[0];
                SCb[SCI(1, 1, 0)] = aR[1]; SCb[SCI(1, 1, 1)] = aZ[1]; SCb[SCI(1, 1, 2)] = aN[1];
                SCb[SCI(1, 2, 0)] = aR[2]; SCb[SCI(1, 2, 1)] = aZ[2]; SCb[SCI(1, 2, 2)] = aN[2];
                SCb[SCI(1, 6, 0)] = aR[6]; SCb[SCI(1, 6, 1)] = aZ[6]; SCb[SCI(1, 6, 2)] = aN[6];
                SCb[SCI(1, 7, 0)] = aR[7]; SCb[SCI(1, 7, 1)] = aZ[7]; SCb[SCI(1, 7, 2)] = aN[7];
            }
            barx(barid);

            // stage x(t+2) into XD[t&1]
            if (t + 2 < T) {
                float v[4] = {xn4.x, xn4.y, xn4.z, xn4.w};
                #pragma unroll
                for (int i = 0; i < 4; ++i)
                    *reinterpret_cast<float2*>(&XD[par * XD_FLOATS + (scol4 + i) * S_DUP + 2 * srow]) =
                        make_float2(v[i], v[i]);
            }

            // ---- epilogue: batch ALL SC/XP loads first, then math ----
            if (grp == 0) {
                u64 s00 = SCb[SCI(1, 0, 0)], s01 = SCb[SCI(1, 0, 1)], s02 = SCb[SCI(1, 0, 2)];
                u64 s10 = SCb[SCI(1, 1, 0)], s11 = SCb[SCI(1, 1, 1)], s12 = SCb[SCI(1, 1, 2)];
                u64 s20 = SCb[SCI(1, 2, 0)], s21 = SCb[SCI(1, 2, 1)], s22 = SCb[SCI(1, 2, 2)];
                u64 x00 = XPb[XPI(par, 0, 0)], x01 = XPb[XPI(par, 0, 1)], x02 = XPb[XPI(par, 0, 2)];
                u64 x10 = XPb[XPI(par, 1, 0)], x11 = XPb[XPI(par, 1, 1)], x12 = XPb[XPI(par, 1, 2)];
                u64 x20 = XPb[XPI(par, 2, 0)], x21 = XPb[XPI(par, 2, 1)], x22 = XPb[XPI(par, 2, 2)];
                gate_row(add2(add2(aR[0], s00), x00), add2(add2(aZ[0], s01), x01),
                         add2(aN[0], s02), x02, gb, h0r);
                gate_row(add2(add2(aR[1], s10), x10), add2(add2(aZ[1], s11), x11),
                         add2(aN[1], s12), x12, gb, h1r);
                gate_row(add2(add2(aR[2], s20), x20), add2(add2(aZ[2], s21), x21),
                         add2(aN[2], s22), x22, gb, h2r);
                HDWR(r0 + 0, h0r)
                HDWR(r0 + 1, h1r)
                HDWR(r0 + 2, h2r)
            } else {
                u64 s00 = SCb[SCI(0, 3, 0)], s01 = SCb[SCI(0, 3, 1)], s02 = SCb[SCI(0, 3, 2)];
                u64 s10 = SCb[SCI(0, 4, 0)], s11 = SCb[SCI(0, 4, 1)], s12 = SCb[SCI(0, 4, 2)];
                u64 s20 = SCb[SCI(0, 5, 0)], s21 = SCb[SCI(0, 5, 1)], s22 = SCb[SCI(0, 5, 2)];
                u64 x00 = XPb[XPI(par, 3, 0)], x01 = XPb[XPI(par, 3, 1)], x02 = XPb[XPI(par, 3, 2)];
                u64 x10 = XPb[XPI(par, 4, 0)], x11 = XPb[XPI(par, 4, 1)], x12 = XPb[XPI(par, 4, 2)];
                u64 x20 = XPb[XPI(par, 5, 0)], x21 = XPb[XPI(par, 5, 1)], x22 = XPb[XPI(par, 5, 2)];
                gate_row(add2(add2(aR[3], s00), x00), add2(add2(aZ[3], s01), x01),
                         add2(aN[3], s02), x02, gb, h0r);
                gate_row(add2(add2(aR[4], s10), x10), add2(add2(aZ[4], s11), x11),
                         add2(aN[4], s12), x12, gb, h1r);
                gate_row(add2(add2(aR[5], s20), x20), add2(add2(aZ[5], s21), x21),
                         add2(aN[5], s22), x22, gb, h2r);
                HDWR(r0 + 3, h0r)
                HDWR(r0 + 4, h1r)
                HDWR(r0 + 5, h2r)
            }
        } else {
            // x-warp: compute XP(t+1)
            u64 aR[8], aZ[8], aX[8];
            #pragma unroll
            for (int i = 0; i < 8; ++i) { aR[i] = 0; aZ[i] = 0; aX[i] = 0; }
            if (t + 1 < T) {
                const float* XDp = XD + par2 * XD_FLOATS;
                #pragma unroll 8
                for (int k = 0; k < I_DIM; ++k) KSTEP_X(k, XDp)
                #pragma unroll
                for (int l = 0; l < 6; ++l) {
                    XPb[XPI(par2, l, 0)] = aR[l];
                    XPb[XPI(par2, l, 1)] = aZ[l];
                    XPb[XPI(par2, l, 2)] = aX[l];
                }
            }
            barx(barid);

            // finish rows 6-7: batch SC loads, then math
            u64 a60 = SCb[SCI(0, 6, 0)], a61 = SCb[SCI(0, 6, 1)], a62 = SCb[SCI(0, 6, 2)];
            u64 b60 = SCb[SCI(1, 6, 0)], b61 = SCb[SCI(1, 6, 1)], b62 = SCb[SCI(1, 6, 2)];
            u64 a70 = SCb[SCI(0, 7, 0)], a71 = SCb[SCI(0, 7, 1)], a72 = SCb[SCI(0, 7, 2)];
            u64 b70 = SCb[SCI(1, 7, 0)], b71 = SCb[SCI(1, 7, 1)], b72 = SCb[SCI(1, 7, 2)];
            gate_row(add2(add2(a60, b60), pR6), add2(add2(a61, b61), pZ6),
                     add2(a62, b62), pX6, gb, h0r);
            gate_row(add2(add2(a70, b70), pR7), add2(add2(a71, b71), pZ7),
                     add2(a72, b72), pX7, gb, h1r);
            HDWR(r0 + 6, h0r)
            HDWR(r0 + 7, h1r)

            pR6 = aR[6]; pZ6 = aZ[6]; pX6 = aX[6];
            pR7 = aR[7]; pZ7 = aZ[7]; pX7 = aX[7];
        }
        barx(barid);
    }

    // ---- final output ----
    if (w < 8) {
        const int base = (grp == 0) ? 0 : 3;
        int b0 = bb + r0 + base;
        *reinterpret_cast<float2*>(&out[(size_t)(b0 + 0) * H_DIM + j0]) = h0r;
        *reinterpret_cast<float2*>(&out[(size_t)(b0 + 1) * H_DIM + j0]) = h1r;
        *reinterpret_cast<float2*>(&out[(size_t)(b0 + 2) * H_DIM + j0]) = h2r;
    } else {
        int b0 = bb + r0 + 6;
        *reinterpret_cast<float2*>(&out[(size_t)(b0 + 0) * H_DIM + j0]) = h0r;
        *reinterpret_cast<float2*>(&out[(size_t)(b0 + 1) * H_DIM + j0]) = h1r;
    }
}

extern "C" void kernel_launch(void* const* d_in, const int* in_sizes, int n_in,
                              void* d_out, int out_size) {
    const float* seq  = (const float*)d_in[0];
    const float* W_ih = (const float*)d_in[1];
    const float* W_hh = (const float*)d_in[2];
    const float* b_ih = (const float*)d_in[3];
    const float* b_hh = (const float*)d_in[4];
    float* out = (float*)d_out;

    const int B = out_size / H_DIM;
    const int T = in_sizes[0] / (B * I_DIM);

    cudaFuncSetAttribute(gru_fwd_kernel,
                         cudaFuncAttributeMaxDynamicSharedMemorySize, SMEM_BYTES);

    const int grid = (B + ROWS_PER_CTA - 1) / ROWS_PER_CTA;
    gru_fwd_kernel<<<grid, THREADS, SMEM_BYTES>>>(seq, W_ih, W_hh, b_ih, b_hh,
                                                  out, B, T);
}